// round 5
// baseline (speedup 1.0000x reference)
#include <cuda_runtime.h>
#include <cuda_bf16.h>
#include <cstdint>

// MeanPooling == batched GEMM + row scale, via mma.sync bf16 hi/lo split.
//   d_in[0] doc_state      [B=32, L=2048, D=256] fp32   (B operand)
//   d_in[1] entity_mapping [B=32, E=256,  L=2048] fp32  (A operand)
//   d_in[2] entity_lens    [B=32, E=256] fp32
// Output [B, E, D] fp32 = (emap @ doc) / lens
//
// x = hi + lo (bf16); x*y ~= hi*hi + hi*lo + lo*hi (fp32 accum).
// CTA tile 128(M) x 64(N), K chunks of 32, double-buffered smem,
// register-prefetch. 256 CTAs, 2 CTAs/SM for cross-CTA latency hiding.

#define BATCH 32
#define E_DIM 256
#define L_DIM 2048
#define D_DIM 256

#define TILE_M 128
#define TILE_N 64
#define CHUNK 32
#define NCHUNK (L_DIM / CHUNK)      // 64

// smem (bf16, strides chosen so consecutive rows shift 16B mod 128 -> no
// ldmatrix bank conflicts): A stride 40 bf16 = 80B, B stride 72 bf16 = 144B.
#define A_STRIDE 40
#define B_STRIDE 72
#define A_SPLIT_BYTES (TILE_M * A_STRIDE * 2)   // 10240
#define B_SPLIT_BYTES (CHUNK * B_STRIDE * 2)    // 4608
#define OFF_A_HI 0
#define OFF_A_LO (A_SPLIT_BYTES)
#define OFF_B_HI (2 * A_SPLIT_BYTES)
#define OFF_B_LO (2 * A_SPLIT_BYTES + B_SPLIT_BYTES)
#define STAGE_BYTES (2 * A_SPLIT_BYTES + 2 * B_SPLIT_BYTES)  // 29696
#define SMEM_TOTAL (2 * STAGE_BYTES)                          // 59392

static __device__ __forceinline__ uint32_t smem_u32(const void* p) {
    uint32_t a;
    asm("{ .reg .u64 t; cvta.to.shared.u64 t, %1; cvt.u32.u64 %0, t; }"
        : "=r"(a) : "l"(p));
    return a;
}

#define LDSM_X4(r0, r1, r2, r3, addr) \
    asm volatile("ldmatrix.sync.aligned.m8n8.x4.shared.b16 {%0,%1,%2,%3}, [%4];" \
                 : "=r"(r0), "=r"(r1), "=r"(r2), "=r"(r3) : "r"(addr))

#define LDSM_X4_T(r0, r1, r2, r3, addr) \
    asm volatile("ldmatrix.sync.aligned.m8n8.x4.trans.shared.b16 {%0,%1,%2,%3}, [%4];" \
                 : "=r"(r0), "=r"(r1), "=r"(r2), "=r"(r3) : "r"(addr))

#define MMA16816(d, a0, a1, a2, a3, b0, b1) \
    asm volatile("mma.sync.aligned.m16n8k16.row.col.f32.bf16.bf16.f32 " \
                 "{%0,%1,%2,%3}, {%4,%5,%6,%7}, {%8,%9}, {%0,%1,%2,%3};" \
                 : "+f"((d)[0]), "+f"((d)[1]), "+f"((d)[2]), "+f"((d)[3]) \
                 : "r"(a0), "r"(a1), "r"(a2), "r"(a3), "r"(b0), "r"(b1))

static __device__ __forceinline__ void split2(float x, float y,
                                              uint32_t& hi, uint32_t& lo)
{
    __nv_bfloat16 hx = __float2bfloat16(x);
    __nv_bfloat16 hy = __float2bfloat16(y);
    __nv_bfloat16 lx = __float2bfloat16(x - __bfloat162float(hx));
    __nv_bfloat16 ly = __float2bfloat16(y - __bfloat162float(hy));
    hi = (uint32_t)__bfloat16_as_ushort(hx) | ((uint32_t)__bfloat16_as_ushort(hy) << 16);
    lo = (uint32_t)__bfloat16_as_ushort(lx) | ((uint32_t)__bfloat16_as_ushort(ly) << 16);
}

__global__ void __launch_bounds__(256, 2)
mean_pool_hmma(const float* __restrict__ doc,
               const float* __restrict__ emap,
               const float* __restrict__ lens,
               float* __restrict__ out)
{
    extern __shared__ char smem[];
    const uint32_t sbase = smem_u32(smem);

    const int tid = threadIdx.x;
    const int wid = tid >> 5;
    const int lid = tid & 31;
    const int wm  = wid & 3;        // 4 warps in M (32 rows each)
    const int wn  = wid >> 2;       // 2 warps in N (32 cols each)

    const int b     = blockIdx.z;
    const int tileM = blockIdx.y * TILE_M;
    const int tileN = blockIdx.x * TILE_N;

    const float* A  = emap + (size_t)b * E_DIM * L_DIM + (size_t)tileM * L_DIM;
    const float* Bm = doc  + (size_t)b * L_DIM * D_DIM + tileN;
    float*       C  = out  + (size_t)b * E_DIM * D_DIM;

    // gmem -> reg load mapping (per chunk of K=32)
    const int a_row = tid >> 1;         // 0..127 (M), 16 floats each
    const int a_k   = (tid & 1) * 16;   // 0/16
    const int b_row = tid >> 3;         // 0..31  (K), 8 floats each
    const int b_n   = (tid & 7) * 8;    // 0..56  (N)

    float acc[2][4][4] = {};            // [m16-tile][n8-tile][frag]
    float4 av[4];
    float4 bv[2];

    // ldmatrix lane addressing
    const uint32_t a_lrow = (uint32_t)(wm * 32 + (lid & 15));
    const uint32_t a_lcol = (uint32_t)((lid >> 4) * 16);             // bytes
    const uint32_t b_lrow = (uint32_t)(lid & 15);
    const uint32_t b_lcol = (uint32_t)(wn * 64 + (lid >> 4) * 16);   // bytes

    // ---- prologue: load + stage chunk 0 ----
    #pragma unroll
    for (int i = 0; i < 4; i++)
        av[i] = *reinterpret_cast<const float4*>(&A[(size_t)a_row * L_DIM + a_k + 4 * i]);
    #pragma unroll
    for (int i = 0; i < 2; i++)
        bv[i] = *reinterpret_cast<const float4*>(&Bm[(size_t)b_row * D_DIM + b_n + 4 * i]);

    {
        char* st = smem;  // stage 0
        uint32_t h[8], l[8];
        #pragma unroll
        for (int i = 0; i < 4; i++) {
            split2(av[i].x, av[i].y, h[2 * i], l[2 * i]);
            split2(av[i].z, av[i].w, h[2 * i + 1], l[2 * i + 1]);
        }
        char* pa = st + OFF_A_HI + a_row * (A_STRIDE * 2) + a_k * 2;
        *reinterpret_cast<uint4*>(pa)      = make_uint4(h[0], h[1], h[2], h[3]);
        *reinterpret_cast<uint4*>(pa + 16) = make_uint4(h[4], h[5], h[6], h[7]);
        pa += (OFF_A_LO - OFF_A_HI);
        *reinterpret_cast<uint4*>(pa)      = make_uint4(l[0], l[1], l[2], l[3]);
        *reinterpret_cast<uint4*>(pa + 16) = make_uint4(l[4], l[5], l[6], l[7]);

        #pragma unroll
        for (int i = 0; i < 2; i++) {
            split2(bv[i].x, bv[i].y, h[2 * i], l[2 * i]);
            split2(bv[i].z, bv[i].w, h[2 * i + 1], l[2 * i + 1]);
        }
        char* pb = st + OFF_B_HI + b_row * (B_STRIDE * 2) + b_n * 2;
        *reinterpret_cast<uint4*>(pb) = make_uint4(h[0], h[1], h[2], h[3]);
        pb += (OFF_B_LO - OFF_B_HI);
        *reinterpret_cast<uint4*>(pb) = make_uint4(l[0], l[1], l[2], l[3]);
    }
    __syncthreads();

    for (int c = 0; c < NCHUNK; c++) {
        const int s = c & 1;

        // prefetch next chunk into registers (overlaps HMMA below)
        if (c + 1 < NCHUNK) {
            const int k0 = (c + 1) * CHUNK;
            #pragma unroll
            for (int i = 0; i < 4; i++)
                av[i] = *reinterpret_cast<const float4*>(
                    &A[(size_t)a_row * L_DIM + k0 + a_k + 4 * i]);
            #pragma unroll
            for (int i = 0; i < 2; i++)
                bv[i] = *reinterpret_cast<const float4*>(
                    &Bm[(size_t)(k0 + b_row) * D_DIM + b_n + 4 * i]);
        }

        // ---- compute on stage s ----
        const uint32_t stg = sbase + (uint32_t)(s * STAGE_BYTES);
        const uint32_t aHi = stg + OFF_A_HI;
        const uint32_t aLo = stg + OFF_A_LO;
        const uint32_t bHi = stg + OFF_B_HI;
        const uint32_t bLo = stg + OFF_B_LO;

        #pragma unroll
        for (int ko = 0; ko < 2; ko++) {            // two k16 steps
            const uint32_t akb = a_lcol + (uint32_t)(ko * 32);
            uint32_t ah[2][4], al[2][4];
            #pragma unroll
            for (int mi = 0; mi < 2; mi++) {
                const uint32_t ao = (a_lrow + mi * 16) * (A_STRIDE * 2) + akb;
                LDSM_X4(ah[mi][0], ah[mi][1], ah[mi][2], ah[mi][3], aHi + ao);
                LDSM_X4(al[mi][0], al[mi][1], al[mi][2], al[mi][3], aLo + ao);
            }
            #pragma unroll
            for (int nt = 0; nt < 2; nt++) {        // two n16 tiles per warp
                const uint32_t bo = (b_lrow + (uint32_t)(ko * 16)) * (B_STRIDE * 2)
                                    + b_lcol + (uint32_t)(nt * 32);
                uint32_t bh0, bh1, bh2, bh3, bl0, bl1, bl2, bl3;
                LDSM_X4_T(bh0, bh1, bh2, bh3, bHi + bo);
                LDSM_X4_T(bl0, bl1, bl2, bl3, bLo + bo);
                #pragma unroll
                for (int mi = 0; mi < 2; mi++) {
                    float* d0 = acc[mi][nt * 2];
                    float* d1 = acc[mi][nt * 2 + 1];
                    MMA16816(d0, ah[mi][0], ah[mi][1], ah[mi][2], ah[mi][3], bh0, bh1);
                    MMA16816(d0, ah[mi][0], ah[mi][1], ah[mi][2], ah[mi][3], bl0, bl1);
                    MMA16816(d0, al[mi][0], al[mi][1], al[mi][2], al[mi][3], bh0, bh1);
                    MMA16816(d1, ah[mi][0], ah[mi][1], ah[mi][2], ah[mi][3], bh2, bh3);
                    MMA16816(d1, ah[mi][0], ah[mi][1], ah[mi][2], ah[mi][3], bl2, bl3);
                    MMA16816(d1, al[mi][0], al[mi][1], al[mi][2], al[mi][3], bh2, bh3);
                }
            }
        }

        // ---- stage chunk c+1 into the other buffer ----
        if (c + 1 < NCHUNK) {
            char* st = smem + (s ^ 1) * STAGE_BYTES;
            uint32_t h[8], l[8];
            #pragma unroll
            for (int i = 0; i < 4; i++) {
                split2(av[i].x, av[i].y, h[2 * i], l[2 * i]);
                split2(av[i].z, av[i].w, h[2 * i + 1], l[2 * i + 1]);
            }
            char* pa = st + OFF_A_HI + a_row * (A_STRIDE * 2) + a_k * 2;
            *reinterpret_cast<uint4*>(pa)      = make_uint4(h[0], h[1], h[2], h[3]);
            *reinterpret_cast<uint4*>(pa + 16) = make_uint4(h[4], h[5], h[6], h[7]);
            pa += (OFF_A_LO - OFF_A_HI);
            *reinterpret_cast<uint4*>(pa)      = make_uint4(l[0], l[1], l[2], l[3]);
            *reinterpret_cast<uint4*>(pa + 16) = make_uint4(l[4], l[5], l[6], l[7]);

            #pragma unroll
            for (int i = 0; i < 2; i++) {
                split2(bv[i].x, bv[i].y, h[2 * i], l[2 * i]);
                split2(bv[i].z, bv[i].w, h[2 * i + 1], l[2 * i + 1]);
            }
            char* pb = st + OFF_B_HI + b_row * (B_STRIDE * 2) + b_n * 2;
            *reinterpret_cast<uint4*>(pb) = make_uint4(h[0], h[1], h[2], h[3]);
            pb += (OFF_B_LO - OFF_B_HI);
            *reinterpret_cast<uint4*>(pb) = make_uint4(l[0], l[1], l[2], l[3]);
        }
        __syncthreads();
    }

    // ---- epilogue: scale by 1/len, store ----
    #pragma unroll
    for (int mi = 0; mi < 2; mi++) {
        const int r0 = tileM + wm * 32 + mi * 16 + (lid >> 2);
        const int r1 = r0 + 8;
        const float inv0 = 1.0f / lens[(size_t)b * E_DIM + r0];
        const float inv1 = 1.0f / lens[(size_t)b * E_DIM + r1];
        #pragma unroll
        for (int j = 0; j < 4; j++) {
            const int col = tileN + wn * 32 + j * 8 + (lid & 3) * 2;
            float2 o0 = make_float2(acc[mi][j][0] * inv0, acc[mi][j][1] * inv0);
            float2 o1 = make_float2(acc[mi][j][2] * inv1, acc[mi][j][3] * inv1);
            *reinterpret_cast<float2*>(&C[(size_t)r0 * D_DIM + col]) = o0;
            *reinterpret_cast<float2*>(&C[(size_t)r1 * D_DIM + col]) = o1;
        }
    }
}

extern "C" void kernel_launch(void* const* d_in, const int* in_sizes, int n_in,
                              void* d_out, int out_size)
{
    const float* doc  = (const float*)d_in[0];
    const float* emap = (const float*)d_in[1];
    const float* lens = (const float*)d_in[2];
    float* out = (float*)d_out;

    cudaFuncSetAttribute(mean_pool_hmma,
                         cudaFuncAttributeMaxDynamicSharedMemorySize, SMEM_TOTAL);

    dim3 grid(D_DIM / TILE_N, E_DIM / TILE_M, BATCH);   // (4, 2, 32) = 256 CTAs
    mean_pool_hmma<<<grid, 256, SMEM_TOTAL>>>(doc, emap, lens, out);
}

// round 6
// speedup vs baseline: 1.0721x; 1.0721x over previous
#include <cuda_runtime.h>
#include <cuda_fp16.h>
#include <cstdint>

// MeanPooling == batched GEMM + row scale, via mma.sync fp16 asymmetric split.
//   d_in[0] doc_state      [B=32, L=2048, D=256] fp32   (B operand)
//   d_in[1] entity_mapping [B=32, E=256,  L=2048] fp32  (A operand)
//   d_in[2] entity_lens    [B=32, E=256] fp32
// Output [B, E, D] fp32 = (emap @ doc) / lens
//
// A = hi + lo (fp16 each, residual ~2^-23); B rounded to single fp16
// (rel 2^-12, random-sign accumulation over K=2048 -> ~1e-4 result error).
// C = A_hi*B + A_lo*B  (2 MMAs, fp32 accumulate).
// CTA tile 128(M) x 64(N), K chunks of 32, double-buffered smem,
// register-prefetch, 256 CTAs, 2 CTAs/SM.

#define BATCH 32
#define E_DIM 256
#define L_DIM 2048
#define D_DIM 256

#define TILE_M 128
#define TILE_N 64
#define CHUNK 32
#define NCHUNK (L_DIM / CHUNK)      // 64

// smem strides (fp16 elems): rows shift 16B mod 128 -> conflict-free ldmatrix.
#define A_STRIDE 40                  // 80B per A row
#define B_STRIDE 72                  // 144B per B row
#define A_SPLIT_BYTES (TILE_M * A_STRIDE * 2)   // 10240
#define B_TILE_BYTES  (CHUNK * B_STRIDE * 2)    // 4608
#define OFF_A_HI 0
#define OFF_A_LO (A_SPLIT_BYTES)
#define OFF_B    (2 * A_SPLIT_BYTES)
#define STAGE_BYTES (2 * A_SPLIT_BYTES + B_TILE_BYTES)   // 25088
#define SMEM_TOTAL (2 * STAGE_BYTES)                      // 50176

static __device__ __forceinline__ uint32_t smem_u32(const void* p) {
    uint32_t a;
    asm("{ .reg .u64 t; cvta.to.shared.u64 t, %1; cvt.u32.u64 %0, t; }"
        : "=r"(a) : "l"(p));
    return a;
}

#define LDSM_X4(r0, r1, r2, r3, addr) \
    asm volatile("ldmatrix.sync.aligned.m8n8.x4.shared.b16 {%0,%1,%2,%3}, [%4];" \
                 : "=r"(r0), "=r"(r1), "=r"(r2), "=r"(r3) : "r"(addr))

#define LDSM_X4_T(r0, r1, r2, r3, addr) \
    asm volatile("ldmatrix.sync.aligned.m8n8.x4.trans.shared.b16 {%0,%1,%2,%3}, [%4];" \
                 : "=r"(r0), "=r"(r1), "=r"(r2), "=r"(r3) : "r"(addr))

#define MMA16816(d, a0, a1, a2, a3, b0, b1) \
    asm volatile("mma.sync.aligned.m16n8k16.row.col.f32.f16.f16.f32 " \
                 "{%0,%1,%2,%3}, {%4,%5,%6,%7}, {%8,%9}, {%0,%1,%2,%3};" \
                 : "+f"((d)[0]), "+f"((d)[1]), "+f"((d)[2]), "+f"((d)[3]) \
                 : "r"(a0), "r"(a1), "r"(a2), "r"(a3), "r"(b0), "r"(b1))

// A: exact split x = hi + lo (fp16 pair packed as b16x2)
static __device__ __forceinline__ void splitA2(float x, float y,
                                               uint32_t& hi, uint32_t& lo)
{
    __half hx = __float2half_rn(x);
    __half hy = __float2half_rn(y);
    __half lx = __float2half_rn(x - __half2float(hx));
    __half ly = __float2half_rn(y - __half2float(hy));
    hi = (uint32_t)__half_as_ushort(hx) | ((uint32_t)__half_as_ushort(hy) << 16);
    lo = (uint32_t)__half_as_ushort(lx) | ((uint32_t)__half_as_ushort(ly) << 16);
}

// B: single fp16 rounding
static __device__ __forceinline__ uint32_t cvtB2(float x, float y)
{
    __half hx = __float2half_rn(x);
    __half hy = __float2half_rn(y);
    return (uint32_t)__half_as_ushort(hx) | ((uint32_t)__half_as_ushort(hy) << 16);
}

__global__ void __launch_bounds__(256, 2)
mean_pool_hmma(const float* __restrict__ doc,
               const float* __restrict__ emap,
               const float* __restrict__ lens,
               float* __restrict__ out)
{
    extern __shared__ char smem[];
    const uint32_t sbase = smem_u32(smem);

    const int tid = threadIdx.x;
    const int wid = tid >> 5;
    const int lid = tid & 31;
    const int wm  = wid & 3;        // 4 warps in M (32 rows each)
    const int wn  = wid >> 2;       // 2 warps in N (32 cols each)

    const int b     = blockIdx.z;
    const int tileM = blockIdx.y * TILE_M;
    const int tileN = blockIdx.x * TILE_N;

    const float* A  = emap + (size_t)b * E_DIM * L_DIM + (size_t)tileM * L_DIM;
    const float* Bm = doc  + (size_t)b * L_DIM * D_DIM + tileN;
    float*       C  = out  + (size_t)b * E_DIM * D_DIM;

    // gmem -> reg load mapping (per chunk of K=32)
    const int a_row = tid >> 1;         // 0..127 (M), 16 floats each
    const int a_k   = (tid & 1) * 16;   // 0/16
    const int b_row = tid >> 3;         // 0..31  (K), 8 floats each
    const int b_n   = (tid & 7) * 8;    // 0..56  (N)

    float acc[2][4][4] = {};            // [m16-tile][n8-tile][frag]
    float4 av[4];
    float4 bv[2];

    // ldmatrix lane addressing
    const uint32_t a_lrow = (uint32_t)(wm * 32 + (lid & 15));
    const uint32_t a_lcol = (uint32_t)((lid >> 4) * 16);             // bytes
    const uint32_t b_lrow = (uint32_t)(lid & 15);
    const uint32_t b_lcol = (uint32_t)(wn * 64 + (lid >> 4) * 16);   // bytes

    // ---- prologue: load + stage chunk 0 ----
    #pragma unroll
    for (int i = 0; i < 4; i++)
        av[i] = *reinterpret_cast<const float4*>(&A[(size_t)a_row * L_DIM + a_k + 4 * i]);
    #pragma unroll
    for (int i = 0; i < 2; i++)
        bv[i] = *reinterpret_cast<const float4*>(&Bm[(size_t)b_row * D_DIM + b_n + 4 * i]);

    {
        char* st = smem;  // stage 0
        uint32_t h[8], l[8];
        #pragma unroll
        for (int i = 0; i < 4; i++) {
            splitA2(av[i].x, av[i].y, h[2 * i], l[2 * i]);
            splitA2(av[i].z, av[i].w, h[2 * i + 1], l[2 * i + 1]);
        }
        char* pa = st + OFF_A_HI + a_row * (A_STRIDE * 2) + a_k * 2;
        *reinterpret_cast<uint4*>(pa)      = make_uint4(h[0], h[1], h[2], h[3]);
        *reinterpret_cast<uint4*>(pa + 16) = make_uint4(h[4], h[5], h[6], h[7]);
        pa += (OFF_A_LO - OFF_A_HI);
        *reinterpret_cast<uint4*>(pa)      = make_uint4(l[0], l[1], l[2], l[3]);
        *reinterpret_cast<uint4*>(pa + 16) = make_uint4(l[4], l[5], l[6], l[7]);

        uint4 bw;
        bw.x = cvtB2(bv[0].x, bv[0].y);
        bw.y = cvtB2(bv[0].z, bv[0].w);
        bw.z = cvtB2(bv[1].x, bv[1].y);
        bw.w = cvtB2(bv[1].z, bv[1].w);
        *reinterpret_cast<uint4*>(st + OFF_B + b_row * (B_STRIDE * 2) + b_n * 2) = bw;
    }
    __syncthreads();

    for (int c = 0; c < NCHUNK; c++) {
        const int s = c & 1;

        // prefetch next chunk into registers (overlaps HMMA below)
        if (c + 1 < NCHUNK) {
            const int k0 = (c + 1) * CHUNK;
            #pragma unroll
            for (int i = 0; i < 4; i++)
                av[i] = *reinterpret_cast<const float4*>(
                    &A[(size_t)a_row * L_DIM + k0 + a_k + 4 * i]);
            #pragma unroll
            for (int i = 0; i < 2; i++)
                bv[i] = *reinterpret_cast<const float4*>(
                    &Bm[(size_t)(k0 + b_row) * D_DIM + b_n + 4 * i]);
        }

        // ---- compute on stage s ----
        const uint32_t stg = sbase + (uint32_t)(s * STAGE_BYTES);
        const uint32_t aHi = stg + OFF_A_HI;
        const uint32_t aLo = stg + OFF_A_LO;
        const uint32_t bTl = stg + OFF_B;

        #pragma unroll
        for (int ko = 0; ko < 2; ko++) {            // two k16 steps
            const uint32_t akb = a_lcol + (uint32_t)(ko * 32);
            uint32_t ah[2][4], al[2][4];
            #pragma unroll
            for (int mi = 0; mi < 2; mi++) {
                const uint32_t ao = (a_lrow + mi * 16) * (A_STRIDE * 2) + akb;
                LDSM_X4(ah[mi][0], ah[mi][1], ah[mi][2], ah[mi][3], aHi + ao);
                LDSM_X4(al[mi][0], al[mi][1], al[mi][2], al[mi][3], aLo + ao);
            }
            #pragma unroll
            for (int nt = 0; nt < 2; nt++) {        // two n16 tiles per warp
                const uint32_t bo = (b_lrow + (uint32_t)(ko * 16)) * (B_STRIDE * 2)
                                    + b_lcol + (uint32_t)(nt * 32);
                uint32_t b0, b1, b2, b3;
                LDSM_X4_T(b0, b1, b2, b3, bTl + bo);
                #pragma unroll
                for (int mi = 0; mi < 2; mi++) {
                    float* d0 = acc[mi][nt * 2];
                    float* d1 = acc[mi][nt * 2 + 1];
                    MMA16816(d0, ah[mi][0], ah[mi][1], ah[mi][2], ah[mi][3], b0, b1);
                    MMA16816(d0, al[mi][0], al[mi][1], al[mi][2], al[mi][3], b0, b1);
                    MMA16816(d1, ah[mi][0], ah[mi][1], ah[mi][2], ah[mi][3], b2, b3);
                    MMA16816(d1, al[mi][0], al[mi][1], al[mi][2], al[mi][3], b2, b3);
                }
            }
        }

        // ---- stage chunk c+1 into the other buffer ----
        if (c + 1 < NCHUNK) {
            char* st = smem + (s ^ 1) * STAGE_BYTES;
            uint32_t h[8], l[8];
            #pragma unroll
            for (int i = 0; i < 4; i++) {
                splitA2(av[i].x, av[i].y, h[2 * i], l[2 * i]);
                splitA2(av[i].z, av[i].w, h[2 * i + 1], l[2 * i + 1]);
            }
            char* pa = st + OFF_A_HI + a_row * (A_STRIDE * 2) + a_k * 2;
            *reinterpret_cast<uint4*>(pa)      = make_uint4(h[0], h[1], h[2], h[3]);
            *reinterpret_cast<uint4*>(pa + 16) = make_uint4(h[4], h[5], h[6], h[7]);
            pa += (OFF_A_LO - OFF_A_HI);
            *reinterpret_cast<uint4*>(pa)      = make_uint4(l[0], l[1], l[2], l[3]);
            *reinterpret_cast<uint4*>(pa + 16) = make_uint4(l[4], l[5], l[6], l[7]);

            uint4 bw;
            bw.x = cvtB2(bv[0].x, bv[0].y);
            bw.y = cvtB2(bv[0].z, bv[0].w);
            bw.z = cvtB2(bv[1].x, bv[1].y);
            bw.w = cvtB2(bv[1].z, bv[1].w);
            *reinterpret_cast<uint4*>(st + OFF_B + b_row * (B_STRIDE * 2) + b_n * 2) = bw;
        }
        __syncthreads();
    }

    // ---- epilogue: scale by 1/len, store ----
    #pragma unroll
    for (int mi = 0; mi < 2; mi++) {
        const int r0 = tileM + wm * 32 + mi * 16 + (lid >> 2);
        const int r1 = r0 + 8;
        const float inv0 = 1.0f / lens[(size_t)b * E_DIM + r0];
        const float inv1 = 1.0f / lens[(size_t)b * E_DIM + r1];
        #pragma unroll
        for (int j = 0; j < 4; j++) {
            const int col = tileN + wn * 32 + j * 8 + (lid & 3) * 2;
            float2 o0 = make_float2(acc[mi][j][0] * inv0, acc[mi][j][1] * inv0);
            float2 o1 = make_float2(acc[mi][j][2] * inv1, acc[mi][j][3] * inv1);
            *reinterpret_cast<float2*>(&C[(size_t)r0 * D_DIM + col]) = o0;
            *reinterpret_cast<float2*>(&C[(size_t)r1 * D_DIM + col]) = o1;
        }
    }
}

extern "C" void kernel_launch(void* const* d_in, const int* in_sizes, int n_in,
                              void* d_out, int out_size)
{
    const float* doc  = (const float*)d_in[0];
    const float* emap = (const float*)d_in[1];
    const float* lens = (const float*)d_in[2];
    float* out = (float*)d_out;

    cudaFuncSetAttribute(mean_pool_hmma,
                         cudaFuncAttributeMaxDynamicSharedMemorySize, SMEM_TOTAL);

    dim3 grid(D_DIM / TILE_N, E_DIM / TILE_M, BATCH);   // (4, 2, 32) = 256 CTAs
    mean_pool_hmma<<<grid, 256, SMEM_TOTAL>>>(doc, emap, lens, out);
}

// round 7
// speedup vs baseline: 1.4743x; 1.3752x over previous
#include <cuda_runtime.h>
#include <cuda_fp16.h>
#include <cstdint>

// MeanPooling == batched GEMM + row scale, all-fp16 mma.sync.
//   d_in[0] doc_state      [B=32, L=2048, D=256] fp32   (B operand)
//   d_in[1] entity_mapping [B=32, E=256,  L=2048] fp32  (A operand)
//   d_in[2] entity_lens    [B=32, E=256] fp32
// Output [B, E, D] fp32 = (emap @ doc) / lens
//
// Both operands rounded to fp16 (rel ~2^-11 each); fp32 accumulate over
// K=2048 with random-sign cancellation -> result rel err ~3e-4 (< 1e-3).
// CTA tile 128(M) x 64(N), K chunks of 32, double-buffered smem,
// line-coalesced gmem loads (4 lines per warp-LDG), 256 CTAs, 2 CTAs/SM.

#define BATCH 32
#define E_DIM 256
#define L_DIM 2048
#define D_DIM 256

#define TILE_M 128
#define TILE_N 64
#define CHUNK 32
#define NCHUNK (L_DIM / CHUNK)      // 64

// smem strides (fp16 elems): rows shift 16B mod 128 -> conflict-free ldmatrix.
#define A_STRIDE 40                  // 80B per A row (32 halfs data)
#define B_STRIDE 72                  // 144B per B row (64 halfs data)
#define A_TILE_BYTES (TILE_M * A_STRIDE * 2)    // 10240
#define B_TILE_BYTES (CHUNK * B_STRIDE * 2)     // 4608
#define OFF_A 0
#define OFF_B A_TILE_BYTES
#define STAGE_BYTES (A_TILE_BYTES + B_TILE_BYTES)   // 14848
#define SMEM_TOTAL (2 * STAGE_BYTES)                 // 29696

static __device__ __forceinline__ uint32_t smem_u32(const void* p) {
    uint32_t a;
    asm("{ .reg .u64 t; cvta.to.shared.u64 t, %1; cvt.u32.u64 %0, t; }"
        : "=r"(a) : "l"(p));
    return a;
}

#define LDSM_X4(r0, r1, r2, r3, addr) \
    asm volatile("ldmatrix.sync.aligned.m8n8.x4.shared.b16 {%0,%1,%2,%3}, [%4];" \
                 : "=r"(r0), "=r"(r1), "=r"(r2), "=r"(r3) : "r"(addr))

#define LDSM_X4_T(r0, r1, r2, r3, addr) \
    asm volatile("ldmatrix.sync.aligned.m8n8.x4.trans.shared.b16 {%0,%1,%2,%3}, [%4];" \
                 : "=r"(r0), "=r"(r1), "=r"(r2), "=r"(r3) : "r"(addr))

#define MMA16816(d, a0, a1, a2, a3, b0, b1) \
    asm volatile("mma.sync.aligned.m16n8k16.row.col.f32.f16.f16.f32 " \
                 "{%0,%1,%2,%3}, {%4,%5,%6,%7}, {%8,%9}, {%0,%1,%2,%3};" \
                 : "+f"((d)[0]), "+f"((d)[1]), "+f"((d)[2]), "+f"((d)[3]) \
                 : "r"(a0), "r"(a1), "r"(a2), "r"(a3), "r"(b0), "r"(b1))

static __device__ __forceinline__ uint32_t cvt2(float x, float y)
{
    __half hx = __float2half_rn(x);
    __half hy = __float2half_rn(y);
    return (uint32_t)__half_as_ushort(hx) | ((uint32_t)__half_as_ushort(hy) << 16);
}

__global__ void __launch_bounds__(256, 2)
mean_pool_hmma(const float* __restrict__ doc,
               const float* __restrict__ emap,
               const float* __restrict__ lens,
               float* __restrict__ out)
{
    extern __shared__ char smem[];
    const uint32_t sbase = smem_u32(smem);

    const int tid = threadIdx.x;
    const int wid = tid >> 5;
    const int lid = tid & 31;
    const int wm  = wid & 3;        // 4 warps in M (32 rows each)
    const int wn  = wid >> 2;       // 2 warps in N (32 cols each)

    const int b     = blockIdx.z;
    const int tileM = blockIdx.y * TILE_M;
    const int tileN = blockIdx.x * TILE_N;

    const float* A  = emap + (size_t)b * E_DIM * L_DIM + (size_t)tileM * L_DIM;
    const float* Bm = doc  + (size_t)b * L_DIM * D_DIM + tileN;
    float*       C  = out  + (size_t)b * E_DIM * D_DIM;

    // gmem load mapping: 8 lanes cover one 128B line per warp instruction.
    const int a_r = tid >> 3;           // 0..31, +32p -> 0..127 (M rows)
    const int a_c = (tid & 7) * 4;      // float col within 32-float window
    const int b_r = tid >> 3;           // 0..31 (K rows)
    const int b_c = (tid & 7) * 4;      // float col; second load at +32

    float acc[2][4][4] = {};            // [m16-tile][n8-tile][frag]
    float4 av[4];                       // A prefetch: rows a_r+32p
    float4 bv[2];                       // B prefetch: cols b_c, b_c+32

    // ldmatrix lane addressing
    const uint32_t a_lrow = (uint32_t)(wm * 32 + (lid & 15));
    const uint32_t a_lcol = (uint32_t)((lid >> 4) * 16);             // bytes
    const uint32_t b_lrow = (uint32_t)(lid & 15);
    const uint32_t b_lcol = (uint32_t)(wn * 64 + (lid >> 4) * 16);   // bytes

    // ---- prologue: load + stage chunk 0 ----
    #pragma unroll
    for (int p = 0; p < 4; p++)
        av[p] = *reinterpret_cast<const float4*>(&A[(size_t)(a_r + 32 * p) * L_DIM + a_c]);
    bv[0] = *reinterpret_cast<const float4*>(&Bm[(size_t)b_r * D_DIM + b_c]);
    bv[1] = *reinterpret_cast<const float4*>(&Bm[(size_t)b_r * D_DIM + b_c + 32]);

    {
        char* st = smem;  // stage 0
        #pragma unroll
        for (int p = 0; p < 4; p++) {
            uint2 w = make_uint2(cvt2(av[p].x, av[p].y), cvt2(av[p].z, av[p].w));
            *reinterpret_cast<uint2*>(st + OFF_A + (a_r + 32 * p) * (A_STRIDE * 2)
                                      + a_c * 2) = w;
        }
        uint2 w0 = make_uint2(cvt2(bv[0].x, bv[0].y), cvt2(bv[0].z, bv[0].w));
        uint2 w1 = make_uint2(cvt2(bv[1].x, bv[1].y), cvt2(bv[1].z, bv[1].w));
        *reinterpret_cast<uint2*>(st + OFF_B + b_r * (B_STRIDE * 2) + b_c * 2)      = w0;
        *reinterpret_cast<uint2*>(st + OFF_B + b_r * (B_STRIDE * 2) + b_c * 2 + 64) = w1;
    }
    __syncthreads();

    for (int c = 0; c < NCHUNK; c++) {
        const int s = c & 1;

        // prefetch next chunk into registers (overlaps HMMA below)
        if (c + 1 < NCHUNK) {
            const int k0 = (c + 1) * CHUNK;
            #pragma unroll
            for (int p = 0; p < 4; p++)
                av[p] = *reinterpret_cast<const float4*>(
                    &A[(size_t)(a_r + 32 * p) * L_DIM + k0 + a_c]);
            bv[0] = *reinterpret_cast<const float4*>(
                &Bm[(size_t)(k0 + b_r) * D_DIM + b_c]);
            bv[1] = *reinterpret_cast<const float4*>(
                &Bm[(size_t)(k0 + b_r) * D_DIM + b_c + 32]);
        }

        // ---- compute on stage s ----
        const uint32_t stg = sbase + (uint32_t)(s * STAGE_BYTES);
        const uint32_t aT  = stg + OFF_A;
        const uint32_t bT  = stg + OFF_B;

        #pragma unroll
        for (int ko = 0; ko < 2; ko++) {            // two k16 steps
            const uint32_t akb = a_lcol + (uint32_t)(ko * 32);
            uint32_t a[2][4];
            #pragma unroll
            for (int mi = 0; mi < 2; mi++) {
                const uint32_t ao = (a_lrow + mi * 16) * (A_STRIDE * 2) + akb;
                LDSM_X4(a[mi][0], a[mi][1], a[mi][2], a[mi][3], aT + ao);
            }
            #pragma unroll
            for (int nt = 0; nt < 2; nt++) {        // two n16 tiles per warp
                const uint32_t bo = (b_lrow + (uint32_t)(ko * 16)) * (B_STRIDE * 2)
                                    + b_lcol + (uint32_t)(nt * 32);
                uint32_t b0, b1, b2, b3;
                LDSM_X4_T(b0, b1, b2, b3, bT + bo);
                #pragma unroll
                for (int mi = 0; mi < 2; mi++) {
                    MMA16816(acc[mi][nt * 2],     a[mi][0], a[mi][1], a[mi][2], a[mi][3], b0, b1);
                    MMA16816(acc[mi][nt * 2 + 1], a[mi][0], a[mi][1], a[mi][2], a[mi][3], b2, b3);
                }
            }
        }

        // ---- stage chunk c+1 into the other buffer ----
        if (c + 1 < NCHUNK) {
            char* st = smem + (s ^ 1) * STAGE_BYTES;
            #pragma unroll
            for (int p = 0; p < 4; p++) {
                uint2 w = make_uint2(cvt2(av[p].x, av[p].y), cvt2(av[p].z, av[p].w));
                *reinterpret_cast<uint2*>(st + OFF_A + (a_r + 32 * p) * (A_STRIDE * 2)
                                          + a_c * 2) = w;
            }
            uint2 w0 = make_uint2(cvt2(bv[0].x, bv[0].y), cvt2(bv[0].z, bv[0].w));
            uint2 w1 = make_uint2(cvt2(bv[1].x, bv[1].y), cvt2(bv[1].z, bv[1].w));
            *reinterpret_cast<uint2*>(st + OFF_B + b_r * (B_STRIDE * 2) + b_c * 2)      = w0;
            *reinterpret_cast<uint2*>(st + OFF_B + b_r * (B_STRIDE * 2) + b_c * 2 + 64) = w1;
        }
        __syncthreads();
    }

    // ---- epilogue: scale by 1/len, store ----
    #pragma unroll
    for (int mi = 0; mi < 2; mi++) {
        const int r0 = tileM + wm * 32 + mi * 16 + (lid >> 2);
        const int r1 = r0 + 8;
        const float inv0 = 1.0f / lens[(size_t)b * E_DIM + r0];
        const float inv1 = 1.0f / lens[(size_t)b * E_DIM + r1];
        #pragma unroll
        for (int j = 0; j < 4; j++) {
            const int col = tileN + wn * 32 + j * 8 + (lid & 3) * 2;
            float2 o0 = make_float2(acc[mi][j][0] * inv0, acc[mi][j][1] * inv0);
            float2 o1 = make_float2(acc[mi][j][2] * inv1, acc[mi][j][3] * inv1);
            *reinterpret_cast<float2*>(&C[(size_t)r0 * D_DIM + col]) = o0;
            *reinterpret_cast<float2*>(&C[(size_t)r1 * D_DIM + col]) = o1;
        }
    }
}

extern "C" void kernel_launch(void* const* d_in, const int* in_sizes, int n_in,
                              void* d_out, int out_size)
{
    const float* doc  = (const float*)d_in[0];
    const float* emap = (const float*)d_in[1];
    const float* lens = (const float*)d_in[2];
    float* out = (float*)d_out;

    cudaFuncSetAttribute(mean_pool_hmma,
                         cudaFuncAttributeMaxDynamicSharedMemorySize, SMEM_TOTAL);

    dim3 grid(D_DIM / TILE_N, E_DIM / TILE_M, BATCH);   // (4, 2, 32) = 256 CTAs
    mean_pool_hmma<<<grid, 256, SMEM_TOTAL>>>(doc, emap, lens, out);
}

// round 8
// speedup vs baseline: 1.6185x; 1.0978x over previous
#include <cuda_runtime.h>
#include <cuda_fp16.h>
#include <cstdint>

// MeanPooling == batched GEMM + row scale, all-fp16 mma.sync with a
// cp.async fp32 staging ring (3 stages) feeding a smem convert pass.
//   d_in[0] doc_state      [B=32, L=2048, D=256] fp32   (B operand)
//   d_in[1] entity_mapping [B=32, E=256,  L=2048] fp32  (A operand)
//   d_in[2] entity_lens    [B=32, E=256] fp32
// Output [B, E, D] fp32 = (emap @ doc) / lens
//
// Pipeline per chunk c:  issue cp.async(c+2) -> compute(c) [ldmatrix+MMA]
// -> wait_group(1) -> convert fp32(c+1) smem->fp16 smem -> bar.
// No LDG->register dependency anywhere in the loop.

#define BATCH 32
#define E_DIM 256
#define L_DIM 2048
#define D_DIM 256

#define TILE_M 128
#define TILE_N 64
#define CHUNK 32
#define NCHUNK (L_DIM / CHUNK)      // 64

// fp32 staging ring: linear tiles, 3 slots
#define A32_BYTES (TILE_M * CHUNK * 4)    // 16384
#define B32_BYTES (CHUNK * TILE_N * 4)    // 8192
#define SLOT_BYTES (A32_BYTES + B32_BYTES) // 24576
#define NSLOT 3
#define RING_BYTES (NSLOT * SLOT_BYTES)    // 73728

// fp16 compute tiles (padded strides, conflict-free ldmatrix)
#define A_STRIDE_B 80                      // bytes per A row (32 halfs + pad)
#define B_STRIDE_B 144                     // bytes per B row (64 halfs + pad)
#define A16_BYTES (TILE_M * A_STRIDE_B)    // 10240
#define B16_BYTES (CHUNK * B_STRIDE_B)     // 4608
#define F16_STAGE (A16_BYTES + B16_BYTES)  // 14848
#define OFF_F16 RING_BYTES
#define SMEM_TOTAL (RING_BYTES + 2 * F16_STAGE)   // 103424

static __device__ __forceinline__ uint32_t smem_u32(const void* p) {
    uint32_t a;
    asm("{ .reg .u64 t; cvta.to.shared.u64 t, %1; cvt.u32.u64 %0, t; }"
        : "=r"(a) : "l"(p));
    return a;
}

#define CP_ASYNC16(smem_addr, gptr) \
    asm volatile("cp.async.cg.shared.global [%0], [%1], 16;" \
                 :: "r"(smem_addr), "l"(gptr) : "memory")
#define CP_COMMIT() asm volatile("cp.async.commit_group;" ::: "memory")
#define CP_WAIT1()  asm volatile("cp.async.wait_group 1;" ::: "memory")

#define LDSM_X4(r0, r1, r2, r3, addr) \
    asm volatile("ldmatrix.sync.aligned.m8n8.x4.shared.b16 {%0,%1,%2,%3}, [%4];" \
                 : "=r"(r0), "=r"(r1), "=r"(r2), "=r"(r3) : "r"(addr))

#define LDSM_X4_T(r0, r1, r2, r3, addr) \
    asm volatile("ldmatrix.sync.aligned.m8n8.x4.trans.shared.b16 {%0,%1,%2,%3}, [%4];" \
                 : "=r"(r0), "=r"(r1), "=r"(r2), "=r"(r3) : "r"(addr))

#define MMA16816(d, a0, a1, a2, a3, b0, b1) \
    asm volatile("mma.sync.aligned.m16n8k16.row.col.f32.f16.f16.f32 " \
                 "{%0,%1,%2,%3}, {%4,%5,%6,%7}, {%8,%9}, {%0,%1,%2,%3};" \
                 : "+f"((d)[0]), "+f"((d)[1]), "+f"((d)[2]), "+f"((d)[3]) \
                 : "r"(a0), "r"(a1), "r"(a2), "r"(a3), "r"(b0), "r"(b1))

static __device__ __forceinline__ uint32_t cvt2(float x, float y)
{
    __half hx = __float2half_rn(x);
    __half hy = __float2half_rn(y);
    return (uint32_t)__half_as_ushort(hx) | ((uint32_t)__half_as_ushort(hy) << 16);
}

__global__ void __launch_bounds__(256, 2)
mean_pool_hmma(const float* __restrict__ doc,
               const float* __restrict__ emap,
               const float* __restrict__ lens,
               float* __restrict__ out)
{
    extern __shared__ char smem[];
    const uint32_t sbase = smem_u32(smem);

    const int tid = threadIdx.x;
    const int wid = tid >> 5;
    const int lid = tid & 31;
    const int wm  = wid & 3;        // 4 warps in M (32 rows each)
    const int wn  = wid >> 2;       // 2 warps in N (32 cols each)

    const int b     = blockIdx.z;
    const int tileM = blockIdx.y * TILE_M;
    const int tileN = blockIdx.x * TILE_N;

    const float* A  = emap + (size_t)b * E_DIM * L_DIM + (size_t)tileM * L_DIM;
    const float* Bm = doc  + (size_t)b * L_DIM * D_DIM + tileN;
    float*       C  = out  + (size_t)b * E_DIM * D_DIM;

    // cp.async source addressing (per 16B unit)
    // A: 1024 units, 4/thread: unit u = tid + 256*i -> row u>>3, col (u&7)*4
    // B: 512 units, 2/thread:  unit u = tid + 256*i -> row u>>4, col (u&15)*4
    const int a_u_row[4] = { (tid + 0)   >> 3, (tid + 256) >> 3,
                             (tid + 512) >> 3, (tid + 768) >> 3 };
    const int a_u_col    = (tid & 7) * 4;
    const int b_u_row[2] = { (tid + 0) >> 4, (tid + 256) >> 4 };
    const int b_u_col    = (tid & 15) * 4;

    float acc[2][4][4] = {};            // [m16-tile][n8-tile][frag]

    // ldmatrix lane addressing (fp16 buffers)
    const uint32_t a_lrow = (uint32_t)(wm * 32 + (lid & 15));
    const uint32_t a_lcol = (uint32_t)((lid >> 4) * 16);             // bytes
    const uint32_t b_lrow = (uint32_t)(lid & 31 & 15);
    const uint32_t b_lcol = (uint32_t)(wn * 64 + (lid >> 4) * 16);   // bytes

    // ---- issue helpers (macros to keep addresses simple) ----
    // issue chunk k0 into ring slot `slot`
    #define ISSUE_CHUNK(k0, slot) do {                                         \
        const uint32_t sA = sbase + (uint32_t)((slot) * SLOT_BYTES);           \
        const uint32_t sB = sA + A32_BYTES;                                    \
        _Pragma("unroll")                                                      \
        for (int i = 0; i < 4; i++) {                                          \
            const int u = tid + 256 * i;                                       \
            CP_ASYNC16(sA + u * 16,                                            \
                       &A[(size_t)a_u_row[i] * L_DIM + (k0) + a_u_col]);       \
        }                                                                      \
        _Pragma("unroll")                                                      \
        for (int i = 0; i < 2; i++) {                                          \
            const int u = tid + 256 * i;                                       \
            CP_ASYNC16(sB + u * 16,                                            \
                       &Bm[(size_t)((k0) + b_u_row[i]) * D_DIM + b_u_col]);    \
        }                                                                      \
    } while (0)

    // convert ring slot -> fp16 buffer buf (0/1)
    #define CONVERT_CHUNK(slot, buf) do {                                      \
        char* srcA = smem + (slot) * SLOT_BYTES;                               \
        char* srcB = srcA + A32_BYTES;                                         \
        char* dstA = smem + OFF_F16 + (buf) * F16_STAGE;                       \
        char* dstB = dstA + A16_BYTES;                                         \
        _Pragma("unroll")                                                      \
        for (int i = 0; i < 8; i++) {                                          \
            const int p = tid + 256 * i;                                       \
            float2 v = *reinterpret_cast<const float2*>(srcA + p * 8);         \
            *reinterpret_cast<uint32_t*>(dstA + (p >> 4) * A_STRIDE_B          \
                                         + (p & 15) * 4) = cvt2(v.x, v.y);     \
        }                                                                      \
        _Pragma("unroll")                                                      \
        for (int i = 0; i < 4; i++) {                                          \
            const int p = tid + 256 * i;                                       \
            float2 v = *reinterpret_cast<const float2*>(srcB + p * 8);         \
            *reinterpret_cast<uint32_t*>(dstB + (p >> 5) * B_STRIDE_B          \
                                         + (p & 31) * 4) = cvt2(v.x, v.y);     \
        }                                                                      \
    } while (0)

    // ---- prologue: chunks 0 and 1 in flight, convert chunk 0 ----
    ISSUE_CHUNK(0, 0);
    CP_COMMIT();
    ISSUE_CHUNK(CHUNK, 1);
    CP_COMMIT();
    CP_WAIT1();                      // chunk 0 resident
    CONVERT_CHUNK(0, 0);
    __syncthreads();

    int slot2 = 2;                   // slot for chunk c+2
    int slot1 = 1;                   // slot for chunk c+1

    for (int c = 0; c < NCHUNK; c++) {
        // issue chunk c+2 (empty commit keeps group accounting uniform)
        if (c + 2 < NCHUNK)
            ISSUE_CHUNK((c + 2) * CHUNK, slot2);
        CP_COMMIT();

        // ---- compute chunk c from fp16 buffer (c&1) ----
        const uint32_t f16 = sbase + OFF_F16 + (uint32_t)((c & 1) * F16_STAGE);
        const uint32_t aT  = f16;
        const uint32_t bT  = f16 + A16_BYTES;

        #pragma unroll
        for (int ko = 0; ko < 2; ko++) {
            const uint32_t akb = a_lcol + (uint32_t)(ko * 32);
            uint32_t a[2][4];
            #pragma unroll
            for (int mi = 0; mi < 2; mi++) {
                const uint32_t ao = (a_lrow + mi * 16) * A_STRIDE_B + akb;
                LDSM_X4(a[mi][0], a[mi][1], a[mi][2], a[mi][3], aT + ao);
            }
            #pragma unroll
            for (int nt = 0; nt < 2; nt++) {
                const uint32_t bo = (b_lrow + (uint32_t)(ko * 16)) * B_STRIDE_B
                                    + b_lcol + (uint32_t)(nt * 32);
                uint32_t b0, b1, b2, b3;
                LDSM_X4_T(b0, b1, b2, b3, bT + bo);
                #pragma unroll
                for (int mi = 0; mi < 2; mi++) {
                    MMA16816(acc[mi][nt * 2],     a[mi][0], a[mi][1], a[mi][2], a[mi][3], b0, b1);
                    MMA16816(acc[mi][nt * 2 + 1], a[mi][0], a[mi][1], a[mi][2], a[mi][3], b2, b3);
                }
            }
        }

        // ---- convert chunk c+1 (its cp.async had >= 1 full chunk to land) ----
        if (c + 1 < NCHUNK) {
            CP_WAIT1();
            CONVERT_CHUNK(slot1, (c + 1) & 1);
        }
        __syncthreads();

        slot1 = slot2;
        slot2 = (slot2 == 2) ? 0 : slot2 + 1;
    }

    // ---- epilogue: scale by 1/len, store ----
    #pragma unroll
    for (int mi = 0; mi < 2; mi++) {
        const int r0 = tileM + wm * 32 + mi * 16 + (lid >> 2);
        const int r1 = r0 + 8;
        const float inv0 = 1.0f / lens[(size_t)b * E_DIM + r0];
        const float inv1 = 1.0f / lens[(size_t)b * E_DIM + r1];
        #pragma unroll
        for (int j = 0; j < 4; j++) {
            const int col = tileN + wn * 32 + j * 8 + (lid & 3) * 2;
            float2 o0 = make_float2(acc[mi][j][0] * inv0, acc[mi][j][1] * inv0);
            float2 o1 = make_float2(acc[mi][j][2] * inv1, acc[mi][j][3] * inv1);
            *reinterpret_cast<float2*>(&C[(size_t)r0 * D_DIM + col]) = o0;
            *reinterpret_cast<float2*>(&C[(size_t)r1 * D_DIM + col]) = o1;
        }
    }
}

extern "C" void kernel_launch(void* const* d_in, const int* in_sizes, int n_in,
                              void* d_out, int out_size)
{
    const float* doc  = (const float*)d_in[0];
    const float* emap = (const float*)d_in[1];
    const float* lens = (const float*)d_in[2];
    float* out = (float*)d_out;

    cudaFuncSetAttribute(mean_pool_hmma,
                         cudaFuncAttributeMaxDynamicSharedMemorySize, SMEM_TOTAL);

    dim3 grid(D_DIM / TILE_N, E_DIM / TILE_M, BATCH);   // (4, 2, 32) = 256 CTAs
    mean_pool_hmma<<<grid, 256, SMEM_TOTAL>>>(doc, emap, lens, out);
}